// round 2
// baseline (speedup 1.0000x reference)
#include <cuda_runtime.h>

#define NN   100000
#define NE   1200000
#define DIM  64
#define NL   3
#define NG   256
#define RHID 128
#define ROUT 32

#define SCAN_CHUNK 1024
#define NB_SCAN ((NN + SCAN_CHUNK - 1) / SCAN_CHUNK)   // 98

// Scratch (__device__ globals: allocation-guard safe)
__device__ float d_h[NL][NN * DIM];          // 76.8 MB
__device__ float d_g[NG * NL * DIM];         // 192 KB
__device__ int   d_deg[NN];
__device__ int   d_rowptr[NN];
__device__ int   d_cursor[NN];
__device__ int   d_csrc[NE];
__device__ int   d_blocksum[128];

// ---------------------------------------------------------------------------
// CSR build: histogram -> 2-level exclusive scan -> cursor fill
// ---------------------------------------------------------------------------
__global__ void zero_deg_kernel() {
    int i = blockIdx.x * blockDim.x + threadIdx.x;
    if (i < NN) d_deg[i] = 0;
}

__global__ void hist_kernel(const int* __restrict__ dst) {
    int e = blockIdx.x * blockDim.x + threadIdx.x;
    if (e < NE) atomicAdd(&d_deg[dst[e]], 1);
}

__global__ void bsum_kernel() {               // grid = NB_SCAN, 256 thr
    __shared__ int ssum[256];
    int b = blockIdx.x, t = threadIdx.x;
    int base = b * SCAN_CHUNK;
    int s = 0;
    for (int i = t; i < SCAN_CHUNK; i += 256) {
        int idx = base + i;
        if (idx < NN) s += d_deg[idx];
    }
    ssum[t] = s; __syncthreads();
    for (int o = 128; o > 0; o >>= 1) {
        if (t < o) ssum[t] += ssum[t + o];
        __syncthreads();
    }
    if (t == 0) d_blocksum[b] = ssum[0];
}

__global__ void scan_bsums_kernel() {         // 1 block, 128 thr
    __shared__ int sb[128];
    int t = threadIdx.x;
    int v = (t < NB_SCAN) ? d_blocksum[t] : 0;
    sb[t] = v; __syncthreads();
    for (int o = 1; o < 128; o <<= 1) {
        int add = (t >= o) ? sb[t - o] : 0;
        __syncthreads();
        sb[t] += add;
        __syncthreads();
    }
    if (t < NB_SCAN) d_blocksum[t] = sb[t] - v;   // exclusive
}

__global__ void scan_chunks_kernel() {        // grid = NB_SCAN, 256 thr
    __shared__ int tsum[256];
    int b = blockIdx.x, t = threadIdx.x;
    int base = b * SCAN_CHUNK;
    int idx0 = base + t * 4;
    int v[4], s = 0;
#pragma unroll
    for (int j = 0; j < 4; j++) {
        int idx = idx0 + j;
        v[j] = (idx < NN) ? d_deg[idx] : 0;
        s += v[j];
    }
    tsum[t] = s; __syncthreads();
    int mine = s;
    for (int o = 1; o < 256; o <<= 1) {
        int add = (t >= o) ? tsum[t - o] : 0;
        __syncthreads();
        tsum[t] += add;
        __syncthreads();
    }
    int run = tsum[t] - mine + d_blocksum[b];
#pragma unroll
    for (int j = 0; j < 4; j++) {
        int idx = idx0 + j;
        if (idx < NN) { d_rowptr[idx] = run; d_cursor[idx] = run; run += v[j]; }
    }
}

__global__ void fill_kernel(const int* __restrict__ src,
                            const int* __restrict__ dst) {
    int e = blockIdx.x * blockDim.x + threadIdx.x;
    if (e < NE) {
        int p = atomicAdd(&d_cursor[dst[e]], 1);
        d_csrc[p] = src[e];
    }
}

// ---------------------------------------------------------------------------
// Fused GIN layer: CSR gather + (1+eps)*h + GEMM(64x64) + bias + ReLU.
// Block = 256 thr, 64 nodes; thread (node=t>>2, cg=t&3) owns 16 output cols.
// ---------------------------------------------------------------------------
#define INS_PAD 68   // 272B rows: 16B-aligned, conflict-free across 8 nodes/warp

__global__ void __launch_bounds__(256, 4)
gin_layer_kernel(const float* __restrict__ x,
                 const float* __restrict__ gW,
                 const float* __restrict__ gB,
                 const float* __restrict__ eps,
                 int layer) {
    __shared__ float Ws[DIM * DIM];          // 16 KB
    __shared__ float ins[64 * INS_PAD];      // 17 KB

    const float* __restrict__ hp = (layer == 0) ? x : d_h[layer - 1];
    int t = threadIdx.x;
    int n0 = blockIdx.x * 64;

    // Stage W (vectorized)
    const float4* Wg = reinterpret_cast<const float4*>(gW + layer * DIM * DIM);
    float4* Wsv = reinterpret_cast<float4*>(Ws);
    for (int i = t; i < DIM * DIM / 4; i += 256) Wsv[i] = Wg[i];

    int node = t >> 2, cg = t & 3;
    int n = n0 + node;
    float e1 = 1.0f + eps[layer];

    // ---- Gather phase: acc = (1+eps)*h[n] + sum_{s in N(n)} h[s], 16 cols ----
    float4 a0 = make_float4(0.f, 0.f, 0.f, 0.f), a1 = a0, a2 = a0, a3 = a0;
    if (n < NN) {
        const float4* own = reinterpret_cast<const float4*>(hp + (size_t)n * DIM + cg * 16);
        float4 o0 = own[0], o1 = own[1], o2 = own[2], o3 = own[3];
        a0 = make_float4(e1 * o0.x, e1 * o0.y, e1 * o0.z, e1 * o0.w);
        a1 = make_float4(e1 * o1.x, e1 * o1.y, e1 * o1.z, e1 * o1.w);
        a2 = make_float4(e1 * o2.x, e1 * o2.y, e1 * o2.z, e1 * o2.w);
        a3 = make_float4(e1 * o3.x, e1 * o3.y, e1 * o3.z, e1 * o3.w);
        int beg = d_rowptr[n], deg = d_deg[n];
        for (int e = 0; e < deg; e++) {
            int s = d_csrc[beg + e];
            const float4* sr = reinterpret_cast<const float4*>(hp + (size_t)s * DIM + cg * 16);
            float4 b0 = sr[0], b1 = sr[1], b2 = sr[2], b3 = sr[3];
            a0.x += b0.x; a0.y += b0.y; a0.z += b0.z; a0.w += b0.w;
            a1.x += b1.x; a1.y += b1.y; a1.z += b1.z; a1.w += b1.w;
            a2.x += b2.x; a2.y += b2.y; a2.z += b2.z; a2.w += b2.w;
            a3.x += b3.x; a3.y += b3.y; a3.z += b3.z; a3.w += b3.w;
        }
    }
    float4* insv = reinterpret_cast<float4*>(&ins[node * INS_PAD + cg * 16]);
    insv[0] = a0; insv[1] = a1; insv[2] = a2; insv[3] = a3;
    __syncthreads();

    // ---- GEMM phase: out[16] = relu(row @ W[:, cg*16:cg*16+16] + b) ----
    float acc[16];
    const float* bias = gB + layer * DIM + cg * 16;
#pragma unroll
    for (int j = 0; j < 16; j++) acc[j] = bias[j];

    const float* ir = &ins[node * INS_PAD];
#pragma unroll
    for (int k4 = 0; k4 < DIM / 4; k4++) {
        float4 a = *reinterpret_cast<const float4*>(ir + k4 * 4);
        float av[4] = {a.x, a.y, a.z, a.w};
#pragma unroll
        for (int kk = 0; kk < 4; kk++) {
            const float4* wr = reinterpret_cast<const float4*>(&Ws[(k4 * 4 + kk) * DIM + cg * 16]);
#pragma unroll
            for (int q = 0; q < 4; q++) {
                float4 w = wr[q];
                acc[4*q+0] = fmaf(av[kk], w.x, acc[4*q+0]);
                acc[4*q+1] = fmaf(av[kk], w.y, acc[4*q+1]);
                acc[4*q+2] = fmaf(av[kk], w.z, acc[4*q+2]);
                acc[4*q+3] = fmaf(av[kk], w.w, acc[4*q+3]);
            }
        }
    }

    if (n < NN) {
        float4* op = reinterpret_cast<float4*>(&d_h[layer][(size_t)n * DIM + cg * 16]);
#pragma unroll
        for (int q = 0; q < 4; q++)
            op[q] = make_float4(fmaxf(acc[4*q+0], 0.f), fmaxf(acc[4*q+1], 0.f),
                                fmaxf(acc[4*q+2], 0.f), fmaxf(acc[4*q+3], 0.f));
    }
}

// ---------------------------------------------------------------------------
// Readout: segmented running sum over sorted graph_ids.
// ---------------------------------------------------------------------------
__global__ void zero_g_kernel() {             // grid 192, block 256 -> 49152
    int i = blockIdx.x * blockDim.x + threadIdx.x;
    d_g[i] = 0.f;
}

#define RO_CHUNK 256
__global__ void readout_kernel(const int* __restrict__ gid) {
    int t   = threadIdx.x;                    // 0..191
    int lay = t >> 6, col = t & 63;
    int n0  = blockIdx.x * RO_CHUNK;
    int nend = min(n0 + RO_CHUNK, NN);
    const float* __restrict__ hp = d_h[lay];

    float acc = 0.f;
    int cur = gid[n0];
    for (int n = n0; n < nend; n++) {
        int gi = gid[n];
        if (gi != cur) {
            atomicAdd(&d_g[cur * (NL * DIM) + t], acc);
            acc = 0.f;
            cur = gi;
        }
        acc += hp[(size_t)n * DIM + col];
    }
    atomicAdd(&d_g[cur * (NL * DIM) + t], acc);
}

// ---------------------------------------------------------------------------
// Readout MLP
// ---------------------------------------------------------------------------
__global__ void mlp_kernel(const float* __restrict__ W1, const float* __restrict__ b1,
                           const float* __restrict__ W2, const float* __restrict__ b2,
                           float* __restrict__ out) {
    int b = blockIdx.x, t = threadIdx.x;      // 192 threads
    __shared__ float gv[NL * DIM];
    __shared__ float hid[RHID];

    gv[t] = d_g[b * (NL * DIM) + t];
    __syncthreads();

    if (t < RHID) {
        float acc = b1[t];
#pragma unroll 4
        for (int k = 0; k < NL * DIM; k++)
            acc = fmaf(gv[k], W1[k * RHID + t], acc);
        hid[t] = fmaxf(acc, 0.f);
    }
    __syncthreads();

    if (t < ROUT) {
        float acc = b2[t];
#pragma unroll 4
        for (int k = 0; k < RHID; k++)
            acc = fmaf(hid[k], W2[k * ROUT + t], acc);
        out[b * ROUT + t] = acc;
    }
}

// ---------------------------------------------------------------------------
extern "C" void kernel_launch(void* const* d_in, const int* in_sizes, int n_in,
                              void* d_out, int out_size) {
    const float* x   = (const float*)d_in[0];
    const float* gW  = (const float*)d_in[1];
    const float* gB  = (const float*)d_in[2];
    const float* eps = (const float*)d_in[3];
    const float* rW1 = (const float*)d_in[4];
    const float* rb1 = (const float*)d_in[5];
    const float* rW2 = (const float*)d_in[6];
    const float* rb2 = (const float*)d_in[7];
    const int*   src = (const int*)d_in[8];
    const int*   dst = (const int*)d_in[9];
    const int*   gid = (const int*)d_in[10];
    float* out = (float*)d_out;

    // CSR build (once per launch)
    zero_deg_kernel<<<(NN + 255) / 256, 256>>>();
    hist_kernel<<<(NE + 255) / 256, 256>>>(dst);
    bsum_kernel<<<NB_SCAN, 256>>>();
    scan_bsums_kernel<<<1, 128>>>();
    scan_chunks_kernel<<<NB_SCAN, 256>>>();
    fill_kernel<<<(NE + 255) / 256, 256>>>(src, dst);

    zero_g_kernel<<<192, 256>>>();

    for (int l = 0; l < NL; l++)
        gin_layer_kernel<<<(NN + 63) / 64, 256>>>(x, gW, gB, eps, l);

    readout_kernel<<<(NN + RO_CHUNK - 1) / RO_CHUNK, 192>>>(gid);
    mlp_kernel<<<NG, 192>>>(rW1, rb1, rW2, rb2, out);
}

// round 5
// speedup vs baseline: 1.9722x; 1.9722x over previous
#include <cuda_runtime.h>

#define NN   100000
#define NE   1200000
#define DIM  64
#define NL   3
#define NG   256
#define RHID 128
#define ROUT 32

#define SCAN_CHUNK 1024
#define NB_SCAN ((NN + SCAN_CHUNK - 1) / SCAN_CHUNK)   // 98

// Scratch (__device__ globals: allocation-guard safe)
__device__ float d_agg[NN * DIM];            // 25.6 MB
__device__ float d_h[NL][NN * DIM];          // 76.8 MB
__device__ float d_g[NG * NL * DIM];         // 192 KB
__device__ int   d_deg[NN];
__device__ int   d_rowptr[NN];
__device__ int   d_cursor[NN];
__device__ int   d_csrc[NE];
__device__ int   d_blocksum[128];

// ---------------------------------------------------------------------------
// CSR build: histogram -> 2-level exclusive scan -> cursor fill
// ---------------------------------------------------------------------------
__global__ void zero_deg_kernel() {
    int i = blockIdx.x * blockDim.x + threadIdx.x;
    if (i < NN) d_deg[i] = 0;
}

__global__ void hist_kernel(const int* __restrict__ dst) {
    int e = blockIdx.x * blockDim.x + threadIdx.x;
    if (e < NE) atomicAdd(&d_deg[dst[e]], 1);
}

__global__ void bsum_kernel() {               // grid = NB_SCAN, 256 thr
    __shared__ int ssum[256];
    int b = blockIdx.x, t = threadIdx.x;
    int base = b * SCAN_CHUNK;
    int s = 0;
    for (int i = t; i < SCAN_CHUNK; i += 256) {
        int idx = base + i;
        if (idx < NN) s += d_deg[idx];
    }
    ssum[t] = s; __syncthreads();
    for (int o = 128; o > 0; o >>= 1) {
        if (t < o) ssum[t] += ssum[t + o];
        __syncthreads();
    }
    if (t == 0) d_blocksum[b] = ssum[0];
}

__global__ void scan_bsums_kernel() {         // 1 block, 128 thr
    __shared__ int sb[128];
    int t = threadIdx.x;
    int v = (t < NB_SCAN) ? d_blocksum[t] : 0;
    sb[t] = v; __syncthreads();
    for (int o = 1; o < 128; o <<= 1) {
        int add = (t >= o) ? sb[t - o] : 0;
        __syncthreads();
        sb[t] += add;
        __syncthreads();
    }
    if (t < NB_SCAN) d_blocksum[t] = sb[t] - v;   // exclusive
}

__global__ void scan_chunks_kernel() {        // grid = NB_SCAN, 256 thr
    __shared__ int tsum[256];
    int b = blockIdx.x, t = threadIdx.x;
    int base = b * SCAN_CHUNK;
    int idx0 = base + t * 4;
    int v[4], s = 0;
#pragma unroll
    for (int j = 0; j < 4; j++) {
        int idx = idx0 + j;
        v[j] = (idx < NN) ? d_deg[idx] : 0;
        s += v[j];
    }
    tsum[t] = s; __syncthreads();
    int mine = s;
    for (int o = 1; o < 256; o <<= 1) {
        int add = (t >= o) ? tsum[t - o] : 0;
        __syncthreads();
        tsum[t] += add;
        __syncthreads();
    }
    int run = tsum[t] - mine + d_blocksum[b];
#pragma unroll
    for (int j = 0; j < 4; j++) {
        int idx = idx0 + j;
        if (idx < NN) { d_rowptr[idx] = run; d_cursor[idx] = run; run += v[j]; }
    }
}

__global__ void fill_kernel(const int* __restrict__ src,
                            const int* __restrict__ dst) {
    int e = blockIdx.x * blockDim.x + threadIdx.x;
    if (e < NE) {
        int p = atomicAdd(&d_cursor[dst[e]], 1);
        d_csrc[p] = src[e];
    }
}

// ---------------------------------------------------------------------------
// Gather: agg[n] = (1+eps)*h[n] + sum_{s in N(n)} h[s].
// One WARP per node; lane owns columns [2*lane, 2*lane+1] (float2).
// Neighbor loop unrolled x4 -> 4 independent coalesced 256B row loads in
// flight per warp -> L2-bandwidth bound, zero atomics, no agg zeroing.
// ---------------------------------------------------------------------------
__global__ void __launch_bounds__(256, 8)
gather_kernel(const float* __restrict__ x,
              const float* __restrict__ eps, int layer) {
    const float* __restrict__ hp = (layer == 0) ? x : d_h[layer - 1];
    int gw   = (blockIdx.x * blockDim.x + threadIdx.x) >> 5;  // global warp = node
    int lane = threadIdx.x & 31;
    if (gw >= NN) return;
    int n = gw;

    float e1 = 1.0f + eps[layer];
    float2 own = reinterpret_cast<const float2*>(hp + (size_t)n * DIM)[lane];
    float ax = e1 * own.x, ay = e1 * own.y;

    int beg = d_rowptr[n];
    int deg = d_deg[n];
    int e = 0;
    for (; e + 4 <= deg; e += 4) {
        int s0 = d_csrc[beg + e + 0];
        int s1 = d_csrc[beg + e + 1];
        int s2 = d_csrc[beg + e + 2];
        int s3 = d_csrc[beg + e + 3];
        float2 v0 = reinterpret_cast<const float2*>(hp + (size_t)s0 * DIM)[lane];
        float2 v1 = reinterpret_cast<const float2*>(hp + (size_t)s1 * DIM)[lane];
        float2 v2 = reinterpret_cast<const float2*>(hp + (size_t)s2 * DIM)[lane];
        float2 v3 = reinterpret_cast<const float2*>(hp + (size_t)s3 * DIM)[lane];
        ax += (v0.x + v1.x) + (v2.x + v3.x);
        ay += (v0.y + v1.y) + (v2.y + v3.y);
    }
    for (; e < deg; e++) {
        int s = d_csrc[beg + e];
        float2 v = reinterpret_cast<const float2*>(hp + (size_t)s * DIM)[lane];
        ax += v.x; ay += v.y;
    }
    reinterpret_cast<float2*>(d_agg + (size_t)n * DIM)[lane] = make_float2(ax, ay);
}

// ---------------------------------------------------------------------------
// GEMM: h[layer] = relu(agg @ W + b).  256 thr = 64 nodes/block.
// Thread (node=t>>2, cg=t&3) owns 16 output cols. launch_bounds caps regs
// at 64 -> 4 blocks (32 warps)/SM, fixing R1's 255-reg / 12.6%-occ pathology.
// ---------------------------------------------------------------------------
#define INS_PAD 68

__global__ void __launch_bounds__(256, 4)
gemm_kernel(const float* __restrict__ gW,
            const float* __restrict__ gB, int layer) {
    __shared__ float Ws[DIM * DIM];          // 16 KB
    __shared__ float ins[64 * INS_PAD];      // 17 KB

    int t  = threadIdx.x;
    int n0 = blockIdx.x * 64;

    const float4* Wg = reinterpret_cast<const float4*>(gW + layer * DIM * DIM);
    float4* Wsv = reinterpret_cast<float4*>(Ws);
    for (int i = t; i < DIM * DIM / 4; i += 256) Wsv[i] = Wg[i];

    // Stage 64 node rows (coalesced: 16 threads cover one 256B row)
    for (int i = t; i < 64 * DIM / 4; i += 256) {
        int node = i >> 4, c4 = (i & 15) << 2;
        int n = n0 + node;
        float4 v = make_float4(0.f, 0.f, 0.f, 0.f);
        if (n < NN) v = *reinterpret_cast<const float4*>(d_agg + (size_t)n * DIM + c4);
        *reinterpret_cast<float4*>(&ins[node * INS_PAD + c4]) = v;
    }
    __syncthreads();

    int node = t >> 2, cg = t & 3;
    float acc[16];
    const float* bias = gB + layer * DIM + cg * 16;
#pragma unroll
    for (int j = 0; j < 16; j++) acc[j] = bias[j];

    const float* ir = &ins[node * INS_PAD];
#pragma unroll 8
    for (int k = 0; k < DIM; k++) {
        float a = ir[k];
        const float4* wr = reinterpret_cast<const float4*>(&Ws[k * DIM + cg * 16]);
        float4 w0 = wr[0], w1 = wr[1], w2 = wr[2], w3 = wr[3];
        acc[0]  = fmaf(a, w0.x, acc[0]);  acc[1]  = fmaf(a, w0.y, acc[1]);
        acc[2]  = fmaf(a, w0.z, acc[2]);  acc[3]  = fmaf(a, w0.w, acc[3]);
        acc[4]  = fmaf(a, w1.x, acc[4]);  acc[5]  = fmaf(a, w1.y, acc[5]);
        acc[6]  = fmaf(a, w1.z, acc[6]);  acc[7]  = fmaf(a, w1.w, acc[7]);
        acc[8]  = fmaf(a, w2.x, acc[8]);  acc[9]  = fmaf(a, w2.y, acc[9]);
        acc[10] = fmaf(a, w2.z, acc[10]); acc[11] = fmaf(a, w2.w, acc[11]);
        acc[12] = fmaf(a, w3.x, acc[12]); acc[13] = fmaf(a, w3.y, acc[13]);
        acc[14] = fmaf(a, w3.z, acc[14]); acc[15] = fmaf(a, w3.w, acc[15]);
    }

    int n = n0 + node;
    if (n < NN) {
        float4* op = reinterpret_cast<float4*>(&d_h[layer][(size_t)n * DIM + cg * 16]);
#pragma unroll
        for (int q = 0; q < 4; q++)
            op[q] = make_float4(fmaxf(acc[4*q+0], 0.f), fmaxf(acc[4*q+1], 0.f),
                                fmaxf(acc[4*q+2], 0.f), fmaxf(acc[4*q+3], 0.f));
    }
}

// ---------------------------------------------------------------------------
// Readout: segmented running sum over sorted graph_ids.
// ---------------------------------------------------------------------------
__global__ void zero_g_kernel() {             // grid 192, block 256 -> 49152
    int i = blockIdx.x * blockDim.x + threadIdx.x;
    d_g[i] = 0.f;
}

#define RO_CHUNK 256
__global__ void readout_kernel(const int* __restrict__ gid) {
    int t   = threadIdx.x;                    // 0..191
    int lay = t >> 6, col = t & 63;
    int n0  = blockIdx.x * RO_CHUNK;
    int nend = min(n0 + RO_CHUNK, NN);
    const float* __restrict__ hp = d_h[lay];

    float acc = 0.f;
    int cur = gid[n0];
    for (int n = n0; n < nend; n++) {
        int gi = gid[n];
        if (gi != cur) {
            atomicAdd(&d_g[cur * (NL * DIM) + t], acc);
            acc = 0.f;
            cur = gi;
        }
        acc += hp[(size_t)n * DIM + col];
    }
    atomicAdd(&d_g[cur * (NL * DIM) + t], acc);
}

// ---------------------------------------------------------------------------
// Readout MLP
// ---------------------------------------------------------------------------
__global__ void mlp_kernel(const float* __restrict__ W1, const float* __restrict__ b1,
                           const float* __restrict__ W2, const float* __restrict__ b2,
                           float* __restrict__ out) {
    int b = blockIdx.x, t = threadIdx.x;      // 192 threads
    __shared__ float gv[NL * DIM];
    __shared__ float hid[RHID];

    gv[t] = d_g[b * (NL * DIM) + t];
    __syncthreads();

    if (t < RHID) {
        float acc = b1[t];
#pragma unroll 4
        for (int k = 0; k < NL * DIM; k++)
            acc = fmaf(gv[k], W1[k * RHID + t], acc);
        hid[t] = fmaxf(acc, 0.f);
    }
    __syncthreads();

    if (t < ROUT) {
        float acc = b2[t];
#pragma unroll 4
        for (int k = 0; k < RHID; k++)
            acc = fmaf(hid[k], W2[k * ROUT + t], acc);
        out[b * ROUT + t] = acc;
    }
}

// ---------------------------------------------------------------------------
extern "C" void kernel_launch(void* const* d_in, const int* in_sizes, int n_in,
                              void* d_out, int out_size) {
    const float* x   = (const float*)d_in[0];
    const float* gW  = (const float*)d_in[1];
    const float* gB  = (const float*)d_in[2];
    const float* eps = (const float*)d_in[3];
    const float* rW1 = (const float*)d_in[4];
    const float* rb1 = (const float*)d_in[5];
    const float* rW2 = (const float*)d_in[6];
    const float* rb2 = (const float*)d_in[7];
    const int*   src = (const int*)d_in[8];
    const int*   dst = (const int*)d_in[9];
    const int*   gid = (const int*)d_in[10];
    float* out = (float*)d_out;

    // CSR build (once per launch)
    zero_deg_kernel<<<(NN + 255) / 256, 256>>>();
    hist_kernel<<<(NE + 255) / 256, 256>>>(dst);
    bsum_kernel<<<NB_SCAN, 256>>>();
    scan_bsums_kernel<<<1, 128>>>();
    scan_chunks_kernel<<<NB_SCAN, 256>>>();
    fill_kernel<<<(NE + 255) / 256, 256>>>(src, dst);

    zero_g_kernel<<<192, 256>>>();

    for (int l = 0; l < NL; l++) {
        gather_kernel<<<(NN * 32 + 255) / 256, 256>>>(x, eps, l);
        gemm_kernel<<<(NN + 63) / 64, 256>>>(gW, gB, l);
    }

    readout_kernel<<<(NN + RO_CHUNK - 1) / RO_CHUNK, 192>>>(gid);
    mlp_kernel<<<NG, 192>>>(rW1, rb1, rW2, rb2, out);
}

// round 6
// speedup vs baseline: 3.8493x; 1.9518x over previous
#include <cuda_runtime.h>

#define NN   100000
#define NE   1200000
#define DIM  64
#define NL   3
#define NG   256
#define RHID 128
#define ROUT 32

#define SCAN_CHUNK 1024
#define NB_SCAN ((NN + SCAN_CHUNK - 1) / SCAN_CHUNK)   // 98

// Scratch (__device__ globals: allocation-guard safe)
__device__ float d_agg[NN * DIM];            // 25.6 MB
__device__ float d_h[NL][NN * DIM];          // 76.8 MB
__device__ float d_g[NG * NL * DIM];         // 192 KB
__device__ int   d_deg[NN];
__device__ int   d_rowptr[NN];
__device__ int   d_cursor[NN];
__device__ int   d_csrc[NE];
__device__ int   d_blocksum[128];

// ---------------------------------------------------------------------------
// CSR build: histogram -> 2-level exclusive scan -> cursor fill
// ---------------------------------------------------------------------------
__global__ void zero_deg_kernel() {
    int i = blockIdx.x * blockDim.x + threadIdx.x;
    if (i < NN) d_deg[i] = 0;
}

__global__ void hist_kernel(const int* __restrict__ dst) {
    int e = blockIdx.x * blockDim.x + threadIdx.x;
    if (e < NE) atomicAdd(&d_deg[dst[e]], 1);
}

__global__ void bsum_kernel() {               // grid = NB_SCAN, 256 thr
    __shared__ int ssum[256];
    int b = blockIdx.x, t = threadIdx.x;
    int base = b * SCAN_CHUNK;
    int s = 0;
    for (int i = t; i < SCAN_CHUNK; i += 256) {
        int idx = base + i;
        if (idx < NN) s += d_deg[idx];
    }
    ssum[t] = s; __syncthreads();
    for (int o = 128; o > 0; o >>= 1) {
        if (t < o) ssum[t] += ssum[t + o];
        __syncthreads();
    }
    if (t == 0) d_blocksum[b] = ssum[0];
}

__global__ void scan_bsums_kernel() {         // 1 block, 128 thr
    __shared__ int sb[128];
    int t = threadIdx.x;
    int v = (t < NB_SCAN) ? d_blocksum[t] : 0;
    sb[t] = v; __syncthreads();
    for (int o = 1; o < 128; o <<= 1) {
        int add = (t >= o) ? sb[t - o] : 0;
        __syncthreads();
        sb[t] += add;
        __syncthreads();
    }
    if (t < NB_SCAN) d_blocksum[t] = sb[t] - v;   // exclusive
}

__global__ void scan_chunks_kernel() {        // grid = NB_SCAN, 256 thr
    __shared__ int tsum[256];
    int b = blockIdx.x, t = threadIdx.x;
    int base = b * SCAN_CHUNK;
    int idx0 = base + t * 4;
    int v[4], s = 0;
#pragma unroll
    for (int j = 0; j < 4; j++) {
        int idx = idx0 + j;
        v[j] = (idx < NN) ? d_deg[idx] : 0;
        s += v[j];
    }
    tsum[t] = s; __syncthreads();
    int mine = s;
    for (int o = 1; o < 256; o <<= 1) {
        int add = (t >= o) ? tsum[t - o] : 0;
        __syncthreads();
        tsum[t] += add;
        __syncthreads();
    }
    int run = tsum[t] - mine + d_blocksum[b];
#pragma unroll
    for (int j = 0; j < 4; j++) {
        int idx = idx0 + j;
        if (idx < NN) { d_rowptr[idx] = run; d_cursor[idx] = run; run += v[j]; }
    }
}

__global__ void fill_kernel(const int* __restrict__ src,
                            const int* __restrict__ dst) {
    int e = blockIdx.x * blockDim.x + threadIdx.x;
    if (e < NE) {
        int p = atomicAdd(&d_cursor[dst[e]], 1);
        d_csrc[p] = src[e];
    }
}

// ---------------------------------------------------------------------------
// Gather: agg[n] = (1+eps)*h[n] + sum_{s in N(n)} h[s].
// One WARP per node; lane owns columns [2*lane, 2*lane+1] (float2).
// ---------------------------------------------------------------------------
__global__ void __launch_bounds__(256, 8)
gather_kernel(const float* __restrict__ x,
              const float* __restrict__ eps, int layer) {
    const float* __restrict__ hp = (layer == 0) ? x : d_h[layer - 1];
    int gw   = (blockIdx.x * blockDim.x + threadIdx.x) >> 5;  // global warp = node
    int lane = threadIdx.x & 31;
    if (gw >= NN) return;
    int n = gw;

    float e1 = 1.0f + eps[layer];
    float2 own = reinterpret_cast<const float2*>(hp + (size_t)n * DIM)[lane];
    float ax = e1 * own.x, ay = e1 * own.y;

    int beg = d_rowptr[n];
    int deg = d_deg[n];
    int e = 0;
    for (; e + 4 <= deg; e += 4) {
        int s0 = d_csrc[beg + e + 0];
        int s1 = d_csrc[beg + e + 1];
        int s2 = d_csrc[beg + e + 2];
        int s3 = d_csrc[beg + e + 3];
        float2 v0 = reinterpret_cast<const float2*>(hp + (size_t)s0 * DIM)[lane];
        float2 v1 = reinterpret_cast<const float2*>(hp + (size_t)s1 * DIM)[lane];
        float2 v2 = reinterpret_cast<const float2*>(hp + (size_t)s2 * DIM)[lane];
        float2 v3 = reinterpret_cast<const float2*>(hp + (size_t)s3 * DIM)[lane];
        ax += (v0.x + v1.x) + (v2.x + v3.x);
        ay += (v0.y + v1.y) + (v2.y + v3.y);
    }
    for (; e < deg; e++) {
        int s = d_csrc[beg + e];
        float2 v = reinterpret_cast<const float2*>(hp + (size_t)s * DIM)[lane];
        ax += v.x; ay += v.y;
    }
    reinterpret_cast<float2*>(d_agg + (size_t)n * DIM)[lane] = make_float2(ax, ay);
}

// ---------------------------------------------------------------------------
// GEMM: h[layer] = relu(agg @ W + b).  Register-blocked 4x4 micro-tile:
// 256 thr, 64x64 tile; thread (tx=t&15, ty=t>>4) owns nodes 4ty..4ty+3 and
// cols 4tx..4tx+3. Per k: 1 LDS.128 (W, conflict-free) + 4 scalar broadcast
// a-reads -> 16 FFMA per ~6 LSU-cyc/warp. FFMA-bound (~28us/layer predicted).
// ---------------------------------------------------------------------------
#define INS_PAD 68

__global__ void __launch_bounds__(256, 4)
gemm_kernel(const float* __restrict__ gW,
            const float* __restrict__ gB, int layer) {
    __shared__ float Ws[DIM * DIM];          // 16 KB
    __shared__ float ins[64 * INS_PAD];      // 17.4 KB

    int t  = threadIdx.x;
    int n0 = blockIdx.x * 64;

    const float4* Wg = reinterpret_cast<const float4*>(gW + layer * DIM * DIM);
    float4* Wsv = reinterpret_cast<float4*>(Ws);
    for (int i = t; i < DIM * DIM / 4; i += 256) Wsv[i] = Wg[i];

    // Stage 64 node rows (coalesced: 16 threads cover one 256B row)
    for (int i = t; i < 64 * DIM / 4; i += 256) {
        int node = i >> 4, c4 = (i & 15) << 2;
        int n = n0 + node;
        float4 v = make_float4(0.f, 0.f, 0.f, 0.f);
        if (n < NN) v = *reinterpret_cast<const float4*>(d_agg + (size_t)n * DIM + c4);
        *reinterpret_cast<float4*>(&ins[node * INS_PAD + c4]) = v;
    }
    __syncthreads();

    int tx = t & 15;          // col group: cols 4tx..4tx+3
    int ty = t >> 4;          // node group: nodes 4ty..4ty+3

    const float* b4 = gB + layer * DIM + 4 * tx;
    float bx = b4[0], by = b4[1], bz = b4[2], bw = b4[3];
    float4 acc0 = make_float4(bx, by, bz, bw);
    float4 acc1 = acc0, acc2 = acc0, acc3 = acc0;

    const float* ir0 = &ins[(4 * ty + 0) * INS_PAD];
    const float* ir1 = &ins[(4 * ty + 1) * INS_PAD];
    const float* ir2 = &ins[(4 * ty + 2) * INS_PAD];
    const float* ir3 = &ins[(4 * ty + 3) * INS_PAD];

#pragma unroll 8
    for (int k = 0; k < DIM; k++) {
        float4 w = *reinterpret_cast<const float4*>(&Ws[k * DIM + 4 * tx]);
        float a0 = ir0[k], a1 = ir1[k], a2 = ir2[k], a3 = ir3[k];
        acc0.x = fmaf(a0, w.x, acc0.x); acc0.y = fmaf(a0, w.y, acc0.y);
        acc0.z = fmaf(a0, w.z, acc0.z); acc0.w = fmaf(a0, w.w, acc0.w);
        acc1.x = fmaf(a1, w.x, acc1.x); acc1.y = fmaf(a1, w.y, acc1.y);
        acc1.z = fmaf(a1, w.z, acc1.z); acc1.w = fmaf(a1, w.w, acc1.w);
        acc2.x = fmaf(a2, w.x, acc2.x); acc2.y = fmaf(a2, w.y, acc2.y);
        acc2.z = fmaf(a2, w.z, acc2.z); acc2.w = fmaf(a2, w.w, acc2.w);
        acc3.x = fmaf(a3, w.x, acc3.x); acc3.y = fmaf(a3, w.y, acc3.y);
        acc3.z = fmaf(a3, w.z, acc3.z); acc3.w = fmaf(a3, w.w, acc3.w);
    }

    float* hl = d_h[layer];
#pragma unroll
    for (int i = 0; i < 4; i++) {
        int n = n0 + 4 * ty + i;
        if (n < NN) {
            float4 a = (i == 0) ? acc0 : (i == 1) ? acc1 : (i == 2) ? acc2 : acc3;
            *reinterpret_cast<float4*>(&hl[(size_t)n * DIM + 4 * tx]) =
                make_float4(fmaxf(a.x, 0.f), fmaxf(a.y, 0.f),
                            fmaxf(a.z, 0.f), fmaxf(a.w, 0.f));
        }
    }
}

// ---------------------------------------------------------------------------
// Readout: segmented running sum over sorted graph_ids.
// ---------------------------------------------------------------------------
__global__ void zero_g_kernel() {             // grid 192, block 256 -> 49152
    int i = blockIdx.x * blockDim.x + threadIdx.x;
    d_g[i] = 0.f;
}

#define RO_CHUNK 128
__global__ void readout_kernel(const int* __restrict__ gid) {
    int t   = threadIdx.x;                    // 0..191
    int lay = t >> 6, col = t & 63;
    int n0  = blockIdx.x * RO_CHUNK;
    int nend = min(n0 + RO_CHUNK, NN);
    const float* __restrict__ hp = d_h[lay];

    float acc = 0.f;
    int cur = gid[n0];
    for (int n = n0; n < nend; n++) {
        int gi = gid[n];
        if (gi != cur) {
            atomicAdd(&d_g[cur * (NL * DIM) + t], acc);
            acc = 0.f;
            cur = gi;
        }
        acc += hp[(size_t)n * DIM + col];
    }
    atomicAdd(&d_g[cur * (NL * DIM) + t], acc);
}

// ---------------------------------------------------------------------------
// Readout MLP
// ---------------------------------------------------------------------------
__global__ void mlp_kernel(const float* __restrict__ W1, const float* __restrict__ b1,
                           const float* __restrict__ W2, const float* __restrict__ b2,
                           float* __restrict__ out) {
    int b = blockIdx.x, t = threadIdx.x;      // 192 threads
    __shared__ float gv[NL * DIM];
    __shared__ float hid[RHID];

    gv[t] = d_g[b * (NL * DIM) + t];
    __syncthreads();

    if (t < RHID) {
        float acc = b1[t];
#pragma unroll 4
        for (int k = 0; k < NL * DIM; k++)
            acc = fmaf(gv[k], W1[k * RHID + t], acc);
        hid[t] = fmaxf(acc, 0.f);
    }
    __syncthreads();

    if (t < ROUT) {
        float acc = b2[t];
#pragma unroll 4
        for (int k = 0; k < RHID; k++)
            acc = fmaf(hid[k], W2[k * ROUT + t], acc);
        out[b * ROUT + t] = acc;
    }
}

// ---------------------------------------------------------------------------
extern "C" void kernel_launch(void* const* d_in, const int* in_sizes, int n_in,
                              void* d_out, int out_size) {
    const float* x   = (const float*)d_in[0];
    const float* gW  = (const float*)d_in[1];
    const float* gB  = (const float*)d_in[2];
    const float* eps = (const float*)d_in[3];
    const float* rW1 = (const float*)d_in[4];
    const float* rb1 = (const float*)d_in[5];
    const float* rW2 = (const float*)d_in[6];
    const float* rb2 = (const float*)d_in[7];
    const int*   src = (const int*)d_in[8];
    const int*   dst = (const int*)d_in[9];
    const int*   gid = (const int*)d_in[10];
    float* out = (float*)d_out;

    // CSR build (once per launch)
    zero_deg_kernel<<<(NN + 255) / 256, 256>>>();
    hist_kernel<<<(NE + 255) / 256, 256>>>(dst);
    bsum_kernel<<<NB_SCAN, 256>>>();
    scan_bsums_kernel<<<1, 128>>>();
    scan_chunks_kernel<<<NB_SCAN, 256>>>();
    fill_kernel<<<(NE + 255) / 256, 256>>>(src, dst);

    zero_g_kernel<<<192, 256>>>();

    for (int l = 0; l < NL; l++) {
        gather_kernel<<<(NN * 32 + 255) / 256, 256>>>(x, eps, l);
        gemm_kernel<<<(NN + 63) / 64, 256>>>(gW, gB, l);
    }

    readout_kernel<<<(NN + RO_CHUNK - 1) / RO_CHUNK, 192>>>(gid);
    mlp_kernel<<<NG, 192>>>(rW1, rb1, rW2, rb2, out);
}

// round 7
// speedup vs baseline: 3.8917x; 1.0110x over previous
#include <cuda_runtime.h>

#define NN   100000
#define NE   1200000
#define DIM  64
#define NL   3
#define NG   256
#define RHID 128
#define ROUT 32

#define SCAN_CHUNK 1024
#define NB_SCAN ((NN + SCAN_CHUNK - 1) / SCAN_CHUNK)   // 98

// Scratch (__device__ globals: allocation-guard safe)
__device__ float d_h[NL][NN * DIM];          // 76.8 MB
__device__ float d_g[NG * NL * DIM];         // 192 KB
__device__ int   d_deg[NN];
__device__ int   d_rowptr[NN];
__device__ int   d_cursor[NN];
__device__ int   d_csrc[NE];
__device__ int   d_blocksum[128];

// ---------------------------------------------------------------------------
// CSR build: histogram -> 2-level exclusive scan -> cursor fill
// ---------------------------------------------------------------------------
__global__ void zero_deg_kernel() {
    int i = blockIdx.x * blockDim.x + threadIdx.x;
    if (i < NN) d_deg[i] = 0;
}

__global__ void hist_kernel(const int* __restrict__ dst) {
    int e = blockIdx.x * blockDim.x + threadIdx.x;
    if (e < NE) atomicAdd(&d_deg[dst[e]], 1);
}

__global__ void bsum_kernel() {               // grid = NB_SCAN, 256 thr
    __shared__ int ssum[256];
    int b = blockIdx.x, t = threadIdx.x;
    int base = b * SCAN_CHUNK;
    int s = 0;
    for (int i = t; i < SCAN_CHUNK; i += 256) {
        int idx = base + i;
        if (idx < NN) s += d_deg[idx];
    }
    ssum[t] = s; __syncthreads();
    for (int o = 128; o > 0; o >>= 1) {
        if (t < o) ssum[t] += ssum[t + o];
        __syncthreads();
    }
    if (t == 0) d_blocksum[b] = ssum[0];
}

__global__ void scan_bsums_kernel() {         // 1 block, 128 thr
    __shared__ int sb[128];
    int t = threadIdx.x;
    int v = (t < NB_SCAN) ? d_blocksum[t] : 0;
    sb[t] = v; __syncthreads();
    for (int o = 1; o < 128; o <<= 1) {
        int add = (t >= o) ? sb[t - o] : 0;
        __syncthreads();
        sb[t] += add;
        __syncthreads();
    }
    if (t < NB_SCAN) d_blocksum[t] = sb[t] - v;   // exclusive
}

__global__ void scan_chunks_kernel() {        // grid = NB_SCAN, 256 thr
    __shared__ int tsum[256];
    int b = blockIdx.x, t = threadIdx.x;
    int base = b * SCAN_CHUNK;
    int idx0 = base + t * 4;
    int v[4], s = 0;
#pragma unroll
    for (int j = 0; j < 4; j++) {
        int idx = idx0 + j;
        v[j] = (idx < NN) ? d_deg[idx] : 0;
        s += v[j];
    }
    tsum[t] = s; __syncthreads();
    int mine = s;
    for (int o = 1; o < 256; o <<= 1) {
        int add = (t >= o) ? tsum[t - o] : 0;
        __syncthreads();
        tsum[t] += add;
        __syncthreads();
    }
    int run = tsum[t] - mine + d_blocksum[b];
#pragma unroll
    for (int j = 0; j < 4; j++) {
        int idx = idx0 + j;
        if (idx < NN) { d_rowptr[idx] = run; d_cursor[idx] = run; run += v[j]; }
    }
}

__global__ void fill_kernel(const int* __restrict__ src,
                            const int* __restrict__ dst) {
    int e = blockIdx.x * blockDim.x + threadIdx.x;
    if (e < NE) {
        int p = atomicAdd(&d_cursor[dst[e]], 1);
        d_csrc[p] = src[e];
    }
}

// ---------------------------------------------------------------------------
// Fused GIN layer.
// Phase 1 (gather): 8 warps x 8 nodes each; lane owns cols [2l, 2l+1].
//   agg = (1+eps)*h[n] + sum h[src]; unroll-4 neighbor loop -> 4 independent
//   256B row loads in flight per warp; result written straight to smem ins[].
//   No d_agg global round-trip (saves 51 MB L2 traffic per layer).
// Phase 2 (gemm): register-blocked 4x4 micro-tile (the R6 winner shape):
//   thread (tx,ty) owns nodes 4ty..4ty+3, cols 4tx..4tx+3; per k:
//   1 LDS.128 (W) + 4 broadcast scalar a-reads -> 16 FFMA.
// ---------------------------------------------------------------------------
#define INS_PAD 68

__global__ void __launch_bounds__(256, 4)
gin_layer_kernel(const float* __restrict__ x,
                 const float* __restrict__ gW,
                 const float* __restrict__ gB,
                 const float* __restrict__ eps, int layer) {
    __shared__ float Ws[DIM * DIM];          // 16 KB
    __shared__ float ins[64 * INS_PAD];      // 17.4 KB

    const float* __restrict__ hp = (layer == 0) ? x : d_h[layer - 1];
    int t  = threadIdx.x;
    int n0 = blockIdx.x * 64;
    int warp = t >> 5, lane = t & 31;

    // Stage W (vectorized, all 256 threads)
    const float4* Wg = reinterpret_cast<const float4*>(gW + layer * DIM * DIM);
    float4* Wsv = reinterpret_cast<float4*>(Ws);
    for (int i = t; i < DIM * DIM / 4; i += 256) Wsv[i] = Wg[i];

    // ---- Phase 1: warp-per-node gather into smem ----
    float e1 = 1.0f + eps[layer];
#pragma unroll
    for (int i = 0; i < 8; i++) {
        int nl = warp * 8 + i;               // local node 0..63
        int n  = n0 + nl;
        float ax = 0.f, ay = 0.f;
        if (n < NN) {
            float2 own = reinterpret_cast<const float2*>(hp + (size_t)n * DIM)[lane];
            ax = e1 * own.x; ay = e1 * own.y;
            int beg = d_rowptr[n];
            int deg = d_deg[n];
            int e = 0;
            for (; e + 4 <= deg; e += 4) {
                int s0 = d_csrc[beg + e + 0];
                int s1 = d_csrc[beg + e + 1];
                int s2 = d_csrc[beg + e + 2];
                int s3 = d_csrc[beg + e + 3];
                float2 v0 = reinterpret_cast<const float2*>(hp + (size_t)s0 * DIM)[lane];
                float2 v1 = reinterpret_cast<const float2*>(hp + (size_t)s1 * DIM)[lane];
                float2 v2 = reinterpret_cast<const float2*>(hp + (size_t)s2 * DIM)[lane];
                float2 v3 = reinterpret_cast<const float2*>(hp + (size_t)s3 * DIM)[lane];
                ax += (v0.x + v1.x) + (v2.x + v3.x);
                ay += (v0.y + v1.y) + (v2.y + v3.y);
            }
            for (; e < deg; e++) {
                int s = d_csrc[beg + e];
                float2 v = reinterpret_cast<const float2*>(hp + (size_t)s * DIM)[lane];
                ax += v.x; ay += v.y;
            }
        }
        *reinterpret_cast<float2*>(&ins[nl * INS_PAD + 2 * lane]) = make_float2(ax, ay);
    }
    __syncthreads();

    // ---- Phase 2: 4x4 register-blocked gemm + bias + ReLU ----
    int tx = t & 15;          // cols 4tx..4tx+3
    int ty = t >> 4;          // nodes 4ty..4ty+3

    const float* b4 = gB + layer * DIM + 4 * tx;
    float4 acc0 = make_float4(b4[0], b4[1], b4[2], b4[3]);
    float4 acc1 = acc0, acc2 = acc0, acc3 = acc0;

    const float* ir0 = &ins[(4 * ty + 0) * INS_PAD];
    const float* ir1 = &ins[(4 * ty + 1) * INS_PAD];
    const float* ir2 = &ins[(4 * ty + 2) * INS_PAD];
    const float* ir3 = &ins[(4 * ty + 3) * INS_PAD];

#pragma unroll 8
    for (int k = 0; k < DIM; k++) {
        float4 w = *reinterpret_cast<const float4*>(&Ws[k * DIM + 4 * tx]);
        float a0 = ir0[k], a1 = ir1[k], a2 = ir2[k], a3 = ir3[k];
        acc0.x = fmaf(a0, w.x, acc0.x); acc0.y = fmaf(a0, w.y, acc0.y);
        acc0.z = fmaf(a0, w.z, acc0.z); acc0.w = fmaf(a0, w.w, acc0.w);
        acc1.x = fmaf(a1, w.x, acc1.x); acc1.y = fmaf(a1, w.y, acc1.y);
        acc1.z = fmaf(a1, w.z, acc1.z); acc1.w = fmaf(a1, w.w, acc1.w);
        acc2.x = fmaf(a2, w.x, acc2.x); acc2.y = fmaf(a2, w.y, acc2.y);
        acc2.z = fmaf(a2, w.z, acc2.z); acc2.w = fmaf(a2, w.w, acc2.w);
        acc3.x = fmaf(a3, w.x, acc3.x); acc3.y = fmaf(a3, w.y, acc3.y);
        acc3.z = fmaf(a3, w.z, acc3.z); acc3.w = fmaf(a3, w.w, acc3.w);
    }

    float* hl = d_h[layer];
#pragma unroll
    for (int i = 0; i < 4; i++) {
        int n = n0 + 4 * ty + i;
        if (n < NN) {
            float4 a = (i == 0) ? acc0 : (i == 1) ? acc1 : (i == 2) ? acc2 : acc3;
            *reinterpret_cast<float4*>(&hl[(size_t)n * DIM + 4 * tx]) =
                make_float4(fmaxf(a.x, 0.f), fmaxf(a.y, 0.f),
                            fmaxf(a.z, 0.f), fmaxf(a.w, 0.f));
        }
    }
}

// ---------------------------------------------------------------------------
// Readout: segmented running sum over sorted graph_ids.
// ---------------------------------------------------------------------------
__global__ void zero_g_kernel() {             // grid 192, block 256 -> 49152
    int i = blockIdx.x * blockDim.x + threadIdx.x;
    d_g[i] = 0.f;
}

#define RO_CHUNK 128
__global__ void readout_kernel(const int* __restrict__ gid) {
    int t   = threadIdx.x;                    // 0..191
    int lay = t >> 6, col = t & 63;
    int n0  = blockIdx.x * RO_CHUNK;
    int nend = min(n0 + RO_CHUNK, NN);
    const float* __restrict__ hp = d_h[lay];

    float acc = 0.f;
    int cur = gid[n0];
    for (int n = n0; n < nend; n++) {
        int gi = gid[n];
        if (gi != cur) {
            atomicAdd(&d_g[cur * (NL * DIM) + t], acc);
            acc = 0.f;
            cur = gi;
        }
        acc += hp[(size_t)n * DIM + col];
    }
    atomicAdd(&d_g[cur * (NL * DIM) + t], acc);
}

// ---------------------------------------------------------------------------
// Readout MLP
// ---------------------------------------------------------------------------
__global__ void mlp_kernel(const float* __restrict__ W1, const float* __restrict__ b1,
                           const float* __restrict__ W2, const float* __restrict__ b2,
                           float* __restrict__ out) {
    int b = blockIdx.x, t = threadIdx.x;      // 192 threads
    __shared__ float gv[NL * DIM];
    __shared__ float hid[RHID];

    gv[t] = d_g[b * (NL * DIM) + t];
    __syncthreads();

    if (t < RHID) {
        float acc = b1[t];
#pragma unroll 4
        for (int k = 0; k < NL * DIM; k++)
            acc = fmaf(gv[k], W1[k * RHID + t], acc);
        hid[t] = fmaxf(acc, 0.f);
    }
    __syncthreads();

    if (t < ROUT) {
        float acc = b2[t];
#pragma unroll 4
        for (int k = 0; k < RHID; k++)
            acc = fmaf(hid[k], W2[k * ROUT + t], acc);
        out[b * ROUT + t] = acc;
    }
}

// ---------------------------------------------------------------------------
extern "C" void kernel_launch(void* const* d_in, const int* in_sizes, int n_in,
                              void* d_out, int out_size) {
    const float* x   = (const float*)d_in[0];
    const float* gW  = (const float*)d_in[1];
    const float* gB  = (const float*)d_in[2];
    const float* eps = (const float*)d_in[3];
    const float* rW1 = (const float*)d_in[4];
    const float* rb1 = (const float*)d_in[5];
    const float* rW2 = (const float*)d_in[6];
    const float* rb2 = (const float*)d_in[7];
    const int*   src = (const int*)d_in[8];
    const int*   dst = (const int*)d_in[9];
    const int*   gid = (const int*)d_in[10];
    float* out = (float*)d_out;

    // CSR build (once per launch)
    zero_deg_kernel<<<(NN + 255) / 256, 256>>>();
    hist_kernel<<<(NE + 255) / 256, 256>>>(dst);
    bsum_kernel<<<NB_SCAN, 256>>>();
    scan_bsums_kernel<<<1, 128>>>();
    scan_chunks_kernel<<<NB_SCAN, 256>>>();
    fill_kernel<<<(NE + 255) / 256, 256>>>(src, dst);

    zero_g_kernel<<<192, 256>>>();

    for (int l = 0; l < NL; l++)
        gin_layer_kernel<<<(NN + 63) / 64, 256>>>(x, gW, gB, eps, l);

    readout_kernel<<<(NN + RO_CHUNK - 1) / RO_CHUNK, 192>>>(gid);
    mlp_kernel<<<NG, 192>>>(rW1, rb1, rW2, rb2, out);
}

// round 13
// speedup vs baseline: 4.1557x; 1.0679x over previous
#include <cuda_runtime.h>
#include <cuda_fp16.h>

#define NN   100000
#define NE   1200000
#define DIM  64
#define NL   3
#define NG   256
#define RHID 128
#define ROUT 32

#define SCAN_CHUNK 1024
#define NB_SCAN ((NN + SCAN_CHUNK - 1) / SCAN_CHUNK)   // 98

// Scratch (__device__ globals: allocation-guard safe)
__device__ __half d_hx[NN * DIM];            // fp16 copy of x (12.8 MB)
__device__ __half d_h[NL][NN * DIM];         // 38.4 MB
__device__ float  d_g[NG * NL * DIM];        // 192 KB
__device__ int    d_deg[NN];
__device__ int    d_rowptr[NN];
__device__ int    d_cursor[NN];
__device__ int    d_csrc[NE];
__device__ int    d_blocksum[128];

// ---------------------------------------------------------------------------
// x -> fp16 conversion (once per launch)
// ---------------------------------------------------------------------------
__global__ void convert_x_kernel(const float* __restrict__ x) {
    int i = blockIdx.x * blockDim.x + threadIdx.x;   // one float4 = 4 elems
    if (i < NN * DIM / 4) {
        float4 v = reinterpret_cast<const float4*>(x)[i];
        __half2 lo = __floats2half2_rn(v.x, v.y);
        __half2 hi = __floats2half2_rn(v.z, v.w);
        reinterpret_cast<uint2*>(d_hx)[i] =
            make_uint2(*reinterpret_cast<unsigned*>(&lo), *reinterpret_cast<unsigned*>(&hi));
    }
}

// ---------------------------------------------------------------------------
// CSR build: histogram -> 2-level exclusive scan -> cursor fill
// ---------------------------------------------------------------------------
__global__ void zero_deg_kernel() {
    int i = blockIdx.x * blockDim.x + threadIdx.x;
    if (i < NN) d_deg[i] = 0;
}

__global__ void hist_kernel(const int* __restrict__ dst) {
    int e = blockIdx.x * blockDim.x + threadIdx.x;
    if (e < NE) atomicAdd(&d_deg[dst[e]], 1);
}

__global__ void bsum_kernel() {               // grid = NB_SCAN, 256 thr
    __shared__ int ssum[256];
    int b = blockIdx.x, t = threadIdx.x;
    int base = b * SCAN_CHUNK;
    int s = 0;
    for (int i = t; i < SCAN_CHUNK; i += 256) {
        int idx = base + i;
        if (idx < NN) s += d_deg[idx];
    }
    ssum[t] = s; __syncthreads();
    for (int o = 128; o > 0; o >>= 1) {
        if (t < o) ssum[t] += ssum[t + o];
        __syncthreads();
    }
    if (t == 0) d_blocksum[b] = ssum[0];
}

__global__ void scan_bsums_kernel() {         // 1 block, 128 thr
    __shared__ int sb[128];
    int t = threadIdx.x;
    int v = (t < NB_SCAN) ? d_blocksum[t] : 0;
    sb[t] = v; __syncthreads();
    for (int o = 1; o < 128; o <<= 1) {
        int add = (t >= o) ? sb[t - o] : 0;
        __syncthreads();
        sb[t] += add;
        __syncthreads();
    }
    if (t < NB_SCAN) d_blocksum[t] = sb[t] - v;   // exclusive
}

__global__ void scan_chunks_kernel() {        // grid = NB_SCAN, 256 thr
    __shared__ int tsum[256];
    int b = blockIdx.x, t = threadIdx.x;
    int base = b * SCAN_CHUNK;
    int idx0 = base + t * 4;
    int v[4], s = 0;
#pragma unroll
    for (int j = 0; j < 4; j++) {
        int idx = idx0 + j;
        v[j] = (idx < NN) ? d_deg[idx] : 0;
        s += v[j];
    }
    tsum[t] = s; __syncthreads();
    int mine = s;
    for (int o = 1; o < 256; o <<= 1) {
        int add = (t >= o) ? tsum[t - o] : 0;
        __syncthreads();
        tsum[t] += add;
        __syncthreads();
    }
    int run = tsum[t] - mine + d_blocksum[b];
#pragma unroll
    for (int j = 0; j < 4; j++) {
        int idx = idx0 + j;
        if (idx < NN) { d_rowptr[idx] = run; d_cursor[idx] = run; run += v[j]; }
    }
}

__global__ void fill_kernel(const int* __restrict__ src,
                            const int* __restrict__ dst) {
    int e = blockIdx.x * blockDim.x + threadIdx.x;
    if (e < NE) {
        int p = atomicAdd(&d_cursor[dst[e]], 1);
        d_csrc[p] = src[e];
    }
}

// ---------------------------------------------------------------------------
// Fused GIN layer (fp16 h storage, fp32 accumulation).
// Phase 1: 8 warps x 8 nodes; lane owns cols [2l, 2l+1] = ONE __half2 (4 B).
//   32 lanes x 4 B = exactly one 128 B fp16 row per warp load (coalesced).
//   Unroll-4 -> 4 rows in flight per warp. fp32 accumulators -> smem fp32.
// Phase 2: register-blocked 4x4 micro-tile gemm (R6 winner), fp16 output
//   (store uses 4*tx, tx<16 -> cols 0..63, in-bounds).
// ---------------------------------------------------------------------------
#define INS_PAD 68

__global__ void __launch_bounds__(256, 4)
gin_layer_kernel(const float* __restrict__ gW,
                 const float* __restrict__ gB,
                 const float* __restrict__ eps, int layer) {
    __shared__ float Ws[DIM * DIM];          // 16 KB
    __shared__ float ins[64 * INS_PAD];      // 17.4 KB

    const __half* __restrict__ hp = (layer == 0) ? d_hx : d_h[layer - 1];
    int t  = threadIdx.x;
    int n0 = blockIdx.x * 64;
    int warp = t >> 5, lane = t & 31;

    // Stage W (vectorized)
    const float4* Wg = reinterpret_cast<const float4*>(gW + layer * DIM * DIM);
    float4* Wsv = reinterpret_cast<float4*>(Ws);
    for (int i = t; i < DIM * DIM / 4; i += 256) Wsv[i] = Wg[i];

    // ---- Phase 1: warp-per-node gather into smem (fp32 accum) ----
    float e1 = 1.0f + eps[layer];
#pragma unroll
    for (int i = 0; i < 8; i++) {
        int nl = warp * 8 + i;               // local node 0..63
        int n  = n0 + nl;
        float ax = 0.f, ay = 0.f;
        if (n < NN) {
            unsigned own = reinterpret_cast<const unsigned*>(hp + (size_t)n * DIM)[lane];
            {
                float2 f = __half22float2(*reinterpret_cast<__half2*>(&own));
                ax = e1 * f.x; ay = e1 * f.y;
            }
            int beg = d_rowptr[n];
            int deg = d_deg[n];
            int e = 0;
            for (; e + 4 <= deg; e += 4) {
                int s0 = d_csrc[beg + e + 0];
                int s1 = d_csrc[beg + e + 1];
                int s2 = d_csrc[beg + e + 2];
                int s3 = d_csrc[beg + e + 3];
                unsigned v0 = reinterpret_cast<const unsigned*>(hp + (size_t)s0 * DIM)[lane];
                unsigned v1 = reinterpret_cast<const unsigned*>(hp + (size_t)s1 * DIM)[lane];
                unsigned v2 = reinterpret_cast<const unsigned*>(hp + (size_t)s2 * DIM)[lane];
                unsigned v3 = reinterpret_cast<const unsigned*>(hp + (size_t)s3 * DIM)[lane];
                float2 f0 = __half22float2(*reinterpret_cast<__half2*>(&v0));
                float2 f1 = __half22float2(*reinterpret_cast<__half2*>(&v1));
                float2 f2 = __half22float2(*reinterpret_cast<__half2*>(&v2));
                float2 f3 = __half22float2(*reinterpret_cast<__half2*>(&v3));
                ax += (f0.x + f1.x) + (f2.x + f3.x);
                ay += (f0.y + f1.y) + (f2.y + f3.y);
            }
            for (; e < deg; e++) {
                int s = d_csrc[beg + e];
                unsigned v = reinterpret_cast<const unsigned*>(hp + (size_t)s * DIM)[lane];
                float2 f = __half22float2(*reinterpret_cast<__half2*>(&v));
                ax += f.x; ay += f.y;
            }
        }
        *reinterpret_cast<float2*>(&ins[nl * INS_PAD + 2 * lane]) = make_float2(ax, ay);
    }
    __syncthreads();

    // ---- Phase 2: 4x4 register-blocked gemm + bias + ReLU -> fp16 ----
    int tx = t & 15;          // cols 4tx..4tx+3 (<= 63)
    int ty = t >> 4;          // nodes 4ty..4ty+3

    const float* b4 = gB + layer * DIM + 4 * tx;
    float4 acc0 = make_float4(b4[0], b4[1], b4[2], b4[3]);
    float4 acc1 = acc0, acc2 = acc0, acc3 = acc0;

    const float* ir0 = &ins[(4 * ty + 0) * INS_PAD];
    const float* ir1 = &ins[(4 * ty + 1) * INS_PAD];
    const float* ir2 = &ins[(4 * ty + 2) * INS_PAD];
    const float* ir3 = &ins[(4 * ty + 3) * INS_PAD];

#pragma unroll 8
    for (int k = 0; k < DIM; k++) {
        float4 w = *reinterpret_cast<const float4*>(&Ws[k * DIM + 4 * tx]);
        float a0 = ir0[k], a1 = ir1[k], a2 = ir2[k], a3 = ir3[k];
        acc0.x = fmaf(a0, w.x, acc0.x); acc0.y = fmaf(a0, w.y, acc0.y);
        acc0.z = fmaf(a0, w.z, acc0.z); acc0.w = fmaf(a0, w.w, acc0.w);
        acc1.x = fmaf(a1, w.x, acc1.x); acc1.y = fmaf(a1, w.y, acc1.y);
        acc1.z = fmaf(a1, w.z, acc1.z); acc1.w = fmaf(a1, w.w, acc1.w);
        acc2.x = fmaf(a2, w.x, acc2.x); acc2.y = fmaf(a2, w.y, acc2.y);
        acc2.z = fmaf(a2, w.z, acc2.z); acc2.w = fmaf(a2, w.w, acc2.w);
        acc3.x = fmaf(a3, w.x, acc3.x); acc3.y = fmaf(a3, w.y, acc3.y);
        acc3.z = fmaf(a3, w.z, acc3.z); acc3.w = fmaf(a3, w.w, acc3.w);
    }

    __half* hl = d_h[layer];
#pragma unroll
    for (int i = 0; i < 4; i++) {
        int n = n0 + 4 * ty + i;
        if (n < NN) {
            float4 a = (i == 0) ? acc0 : (i == 1) ? acc1 : (i == 2) ? acc2 : acc3;
            __half2 lo = __floats2half2_rn(fmaxf(a.x, 0.f), fmaxf(a.y, 0.f));
            __half2 hi = __floats2half2_rn(fmaxf(a.z, 0.f), fmaxf(a.w, 0.f));
            reinterpret_cast<uint2*>(hl + (size_t)n * DIM + 4 * tx)[0] =
                make_uint2(*reinterpret_cast<unsigned*>(&lo), *reinterpret_cast<unsigned*>(&hi));
        }
    }
}

// ---------------------------------------------------------------------------
// Readout: segmented running sum over sorted graph_ids (fp16 in, fp32 accum).
// ---------------------------------------------------------------------------
__global__ void zero_g_kernel() {             // grid 192, block 256 -> 49152
    int i = blockIdx.x * blockDim.x + threadIdx.x;
    d_g[i] = 0.f;
}

#define RO_CHUNK 128
__global__ void readout_kernel(const int* __restrict__ gid) {
    int t   = threadIdx.x;                    // 0..191
    int lay = t >> 6, col = t & 63;
    int n0  = blockIdx.x * RO_CHUNK;
    int nend = min(n0 + RO_CHUNK, NN);
    const __half* __restrict__ hp = d_h[lay];

    float acc = 0.f;
    int cur = gid[n0];
    for (int n = n0; n < nend; n++) {
        int gi = gid[n];
        if (gi != cur) {
            atomicAdd(&d_g[cur * (NL * DIM) + t], acc);
            acc = 0.f;
            cur = gi;
        }
        acc += __half2float(hp[(size_t)n * DIM + col]);
    }
    atomicAdd(&d_g[cur * (NL * DIM) + t], acc);
}

// ---------------------------------------------------------------------------
// Readout MLP
// ---------------------------------------------------------------------------
__global__ void mlp_kernel(const float* __restrict__ W1, const float* __restrict__ b1,
                           const float* __restrict__ W2, const float* __restrict__ b2,
                           float* __restrict__ out) {
    int b = blockIdx.x, t = threadIdx.x;      // 192 threads
    __shared__ float gv[NL * DIM];
    __shared__ float hid[RHID];

    gv[t] = d_g[b * (NL * DIM) + t];
    __syncthreads();

    if (t < RHID) {
        float acc = b1[t];
#pragma unroll 4
        for (int k = 0; k < NL * DIM; k++)
            acc = fmaf(gv[k], W1[k * RHID + t], acc);
        hid[t] = fmaxf(acc, 0.f);
    }
    __syncthreads();

    if (t < ROUT) {
        float acc = b2[t];
#pragma unroll 4
        for (int k = 0; k < RHID; k++)
            acc = fmaf(hid[k], W2[k * ROUT + t], acc);
        out[b * ROUT + t] = acc;
    }
}

// ---------------------------------------------------------------------------
extern "C" void kernel_launch(void* const* d_in, const int* in_sizes, int n_in,
                              void* d_out, int out_size) {
    const float* x   = (const float*)d_in[0];
    const float* gW  = (const float*)d_in[1];
    const float* gB  = (const float*)d_in[2];
    const float* eps = (const float*)d_in[3];
    const float* rW1 = (const float*)d_in[4];
    const float* rb1 = (const float*)d_in[5];
    const float* rW2 = (const float*)d_in[6];
    const float* rb2 = (const float*)d_in[7];
    const int*   src = (const int*)d_in[8];
    const int*   dst = (const int*)d_in[9];
    const int*   gid = (const int*)d_in[10];
    float* out = (float*)d_out;

    // CSR build + x conversion (once per launch)
    zero_deg_kernel<<<(NN + 255) / 256, 256>>>();
    hist_kernel<<<(NE + 255) / 256, 256>>>(dst);
    convert_x_kernel<<<(NN * DIM / 4 + 255) / 256, 256>>>(x);
    bsum_kernel<<<NB_SCAN, 256>>>();
    scan_bsums_kernel<<<1, 128>>>();
    scan_chunks_kernel<<<NB_SCAN, 256>>>();
    fill_kernel<<<(NE + 255) / 256, 256>>>(src, dst);

    zero_g_kernel<<<192, 256>>>();

    for (int l = 0; l < NL; l++)
        gin_layer_kernel<<<(NN + 63) / 64, 256>>>(gW, gB, eps, l);

    readout_kernel<<<(NN + RO_CHUNK - 1) / RO_CHUNK, 192>>>(gid);
    mlp_kernel<<<NG, 192>>>(rW1, rb1, rW2, rb2, out);
}